// round 1
// baseline (speedup 1.0000x reference)
#include <cuda_runtime.h>
#include <cstdint>

// ---------------------------------------------------------------------------
// Problem constants (shapes are fixed by setup_inputs)
// ---------------------------------------------------------------------------
#define B_   64
#define NTOK 384
#define C_   768
#define H_   12
#define D_   64
#define LT   128
#define LS   256

// ---------------------------------------------------------------------------
// Scratch (device globals; allocation-free kernel_launch)
// ---------------------------------------------------------------------------
__device__ __align__(16) float g_Q [(size_t)B_ * H_ * NTOK * D_];
__device__ __align__(16) float g_K [(size_t)B_ * H_ * NTOK * D_];
__device__ __align__(16) float g_V [(size_t)B_ * H_ * NTOK * D_];
__device__ __align__(16) float g_Qh[(size_t)B_ * H_ * NTOK * D_];
__device__ __align__(16) float g_Kh[(size_t)B_ * H_ * NTOK * D_];
__device__ __align__(16) float g_Vh[(size_t)B_ * H_ * NTOK * D_];
__device__ __align__(16) float g_XA [(size_t)B_ * NTOK * C_];  // concat(x_mt, x_s)
__device__ __align__(16) float g_XSh[(size_t)B_ * LS   * C_];  // x_s_hsi

// ---------------------------------------------------------------------------
// tf32 helpers
// ---------------------------------------------------------------------------
__device__ __forceinline__ unsigned f2tf32(float x) {
    unsigned r;
    asm("cvt.rna.tf32.f32 %0, %1;" : "=r"(r) : "f"(x));
    return r;
}

__device__ __forceinline__ void mma_tf32(float c[4],
    unsigned a0, unsigned a1, unsigned a2, unsigned a3,
    unsigned b0, unsigned b1)
{
    asm volatile(
        "mma.sync.aligned.m16n8k8.row.col.f32.tf32.tf32.f32 "
        "{%0,%1,%2,%3}, {%4,%5,%6,%7}, {%8,%9}, {%0,%1,%2,%3};\n"
        : "+f"(c[0]), "+f"(c[1]), "+f"(c[2]), "+f"(c[3])
        : "r"(a0), "r"(a1), "r"(a2), "r"(a3), "r"(b0), "r"(b1));
}

// ---------------------------------------------------------------------------
// GEMM: C[M,Nc] = A[M,768] * W[Nc,768]^T  (both K-major, tf32 MMA, fp32 accum)
// MODE 0: QKV scatter into [B,H,N,D] tensors (p0=Q, p1=K, p2=V)
// MODE 1: proj of g_XA -> out (p0), duplicate rows n<128 into out_hsi (p1), +bias
// MODE 2: proj of g_XSh -> out_hsi rows 128.. (p0), +bias
// ---------------------------------------------------------------------------
template <int MODE>
__global__ __launch_bounds__(256)
void gemm_tf32_kernel(const float* __restrict__ A, const float* __restrict__ W,
                      float* __restrict__ p0, float* __restrict__ p1,
                      float* __restrict__ p2, const float* __restrict__ bias)
{
    __shared__ unsigned As[128][36];
    __shared__ unsigned Bs[128][36];

    const int bm  = blockIdx.y * 128;
    const int bn  = blockIdx.x * 128;
    const int tid = threadIdx.x;
    const int wid = tid >> 5, lane = tid & 31;
    const int wm  = wid & 3, wn = wid >> 2;          // warp tile: 32m x 64n
    const int gid = lane >> 2, tig = lane & 3;

    float acc[2][8][4];
#pragma unroll
    for (int a = 0; a < 2; a++)
#pragma unroll
        for (int b = 0; b < 8; b++)
#pragma unroll
            for (int c = 0; c < 4; c++) acc[a][b][c] = 0.f;

    for (int kb = 0; kb < 768; kb += 32) {
#pragma unroll
        for (int i = 0; i < 4; i++) {
            int idx = tid + i * 256;
            int r = idx >> 3, c4 = (idx & 7) << 2;
            float4 av = *reinterpret_cast<const float4*>(A + (size_t)(bm + r) * 768 + kb + c4);
            *reinterpret_cast<uint4*>(&As[r][c4]) =
                make_uint4(f2tf32(av.x), f2tf32(av.y), f2tf32(av.z), f2tf32(av.w));
            float4 bv = *reinterpret_cast<const float4*>(W + (size_t)(bn + r) * 768 + kb + c4);
            *reinterpret_cast<uint4*>(&Bs[r][c4]) =
                make_uint4(f2tf32(bv.x), f2tf32(bv.y), f2tf32(bv.z), f2tf32(bv.w));
        }
        __syncthreads();
#pragma unroll
        for (int ks = 0; ks < 4; ks++) {
            const int k0 = ks * 8;
            unsigned af[2][4], bf[8][2];
#pragma unroll
            for (int mi = 0; mi < 2; mi++) {
                int m = wm * 32 + mi * 16;
                af[mi][0] = As[m + gid    ][k0 + tig];
                af[mi][1] = As[m + gid + 8][k0 + tig];
                af[mi][2] = As[m + gid    ][k0 + tig + 4];
                af[mi][3] = As[m + gid + 8][k0 + tig + 4];
            }
#pragma unroll
            for (int ni = 0; ni < 8; ni++) {
                int n = wn * 64 + ni * 8;
                bf[ni][0] = Bs[n + gid][k0 + tig];
                bf[ni][1] = Bs[n + gid][k0 + tig + 4];
            }
#pragma unroll
            for (int mi = 0; mi < 2; mi++)
#pragma unroll
                for (int ni = 0; ni < 8; ni++)
                    mma_tf32(acc[mi][ni], af[mi][0], af[mi][1], af[mi][2], af[mi][3],
                             bf[ni][0], bf[ni][1]);
        }
        __syncthreads();
    }

    // epilogue: fragment (row: gid / gid+8, col: 2*tig / 2*tig+1)
#pragma unroll
    for (int mi = 0; mi < 2; mi++) {
#pragma unroll
        for (int ni = 0; ni < 8; ni++) {
            const int row = bm + wm * 32 + mi * 16 + gid;
            const int col = bn + wn * 64 + ni * 8 + tig * 2;
#pragma unroll
            for (int half = 0; half < 2; half++) {
                const int r  = row + half * 8;
                const float v0 = acc[mi][ni][half * 2 + 0];
                const float v1 = acc[mi][ni][half * 2 + 1];
                if (MODE == 0) {
                    int t = col / 768;
                    int rem = col - t * 768;
                    int h = rem >> 6, d = rem & 63;
                    int b = r / 384, n = r - b * 384;
                    float* dst = (t == 0) ? p0 : ((t == 1) ? p1 : p2);
                    *reinterpret_cast<float2*>(
                        dst + ((((size_t)b * H_ + h) * NTOK + n) << 6) + d) =
                        make_float2(v0, v1);
                } else if (MODE == 1) {
                    float2 v = make_float2(v0 + bias[col], v1 + bias[col + 1]);
                    *reinterpret_cast<float2*>(p0 + (size_t)r * 768 + col) = v;
                    int n = r - (r / 384) * 384;
                    if (n < LT)
                        *reinterpret_cast<float2*>(p1 + (size_t)r * 768 + col) = v;
                } else {
                    float2 v = make_float2(v0 + bias[col], v1 + bias[col + 1]);
                    int b = r >> 8;          // / 256
                    int q = r & 255;
                    *reinterpret_cast<float2*>(
                        p0 + ((size_t)b * NTOK + LT + q) * 768 + col) = v;
                }
            }
        }
    }
}

// ---------------------------------------------------------------------------
// Flash attention (fp32): one CTA = 64 queries of one (b,h); 32-key chunks.
// grid = (numQTiles, H, B). Output written as [b][row][h*64+d] (post-transpose
// concat layout), row = outRow0 + local query index.
// ---------------------------------------------------------------------------
__global__ __launch_bounds__(256)
void attn_kernel(const float* __restrict__ Qt, const float* __restrict__ Kt,
                 const float* __restrict__ Vt, float* __restrict__ Out,
                 int q0, int Lk, int outRows, int outRow0)
{
    const int qt = blockIdx.x, h = blockIdx.y, b = blockIdx.z;
    const int tid = threadIdx.x;
    const int tq = tid >> 4;        // 0..15 : owns q rows tq*4 + {0..3}
    const int ts = tid & 15;        // k-cols {ts, ts+16} in S phase; d-cols ts*4.. in PV

    __shared__ float Qs[64][68];    // [q][d]
    __shared__ float Ks[32][68];    // [k][d]
    __shared__ float Vs[32][64];    // [k][d]
    __shared__ float Ps[64][36];    // [q][k]

    const float* Qbh = Qt + (((size_t)b * H_ + h) * NTOK + q0 + qt * 64) * D_;
    const float* Kbh = Kt + (((size_t)b * H_ + h) * NTOK) * D_;
    const float* Vbh = Vt + (((size_t)b * H_ + h) * NTOK) * D_;

    const float scale = 0.125f;     // Dh^-0.5, folded into Q

    // Load (pre-scaled) Q tile
#pragma unroll
    for (int i = 0; i < 4; i++) {
        int idx = tid + i * 256;
        int r = idx >> 4, c4 = (idx & 15) << 2;
        float4 v = *reinterpret_cast<const float4*>(Qbh + r * D_ + c4);
        v.x *= scale; v.y *= scale; v.z *= scale; v.w *= scale;
        *reinterpret_cast<float4*>(&Qs[r][c4]) = v;
    }

    float m_i[4], l_i[4], o[4][4];
#pragma unroll
    for (int i = 0; i < 4; i++) {
        m_i[i] = -1e30f; l_i[i] = 0.f;
#pragma unroll
        for (int j = 0; j < 4; j++) o[i][j] = 0.f;
    }

    for (int kb = 0; kb < Lk; kb += 32) {
        __syncthreads();   // previous PV done reading Ks/Vs/Ps
#pragma unroll
        for (int i = 0; i < 2; i++) {
            int idx = tid + i * 256;
            int r = idx >> 4, c4 = (idx & 15) << 2;
            *reinterpret_cast<float4*>(&Ks[r][c4]) =
                *reinterpret_cast<const float4*>(Kbh + (size_t)(kb + r) * D_ + c4);
            *reinterpret_cast<float4*>(&Vs[r][c4]) =
                *reinterpret_cast<const float4*>(Vbh + (size_t)(kb + r) * D_ + c4);
        }
        __syncthreads();

        // S = (Q*scale) K^T : 4q x 2k per thread, outer product over d
        float s0[4] = {0.f, 0.f, 0.f, 0.f};
        float s1[4] = {0.f, 0.f, 0.f, 0.f};
#pragma unroll 4
        for (int dd = 0; dd < 64; dd += 4) {
            float4 ka = *reinterpret_cast<const float4*>(&Ks[ts][dd]);
            float4 kc = *reinterpret_cast<const float4*>(&Ks[ts + 16][dd]);
#pragma unroll
            for (int i = 0; i < 4; i++) {
                float4 qv = *reinterpret_cast<const float4*>(&Qs[tq * 4 + i][dd]);
                s0[i] += qv.x * ka.x + qv.y * ka.y + qv.z * ka.z + qv.w * ka.w;
                s1[i] += qv.x * kc.x + qv.y * kc.y + qv.z * kc.z + qv.w * kc.w;
            }
        }

        // Online softmax (stats reduced over the 16-thread row group)
#pragma unroll
        for (int i = 0; i < 4; i++) {
            float mx = fmaxf(s0[i], s1[i]);
#pragma unroll
            for (int off = 1; off < 16; off <<= 1)
                mx = fmaxf(mx, __shfl_xor_sync(0xffffffffu, mx, off));
            float m_new = fmaxf(m_i[i], mx);
            float corr = __expf(m_i[i] - m_new);
            float pA = __expf(s0[i] - m_new);
            float pB = __expf(s1[i] - m_new);
            float ls = pA + pB;
#pragma unroll
            for (int off = 1; off < 16; off <<= 1)
                ls += __shfl_xor_sync(0xffffffffu, ls, off);
            l_i[i] = l_i[i] * corr + ls;
            m_i[i] = m_new;
#pragma unroll
            for (int j = 0; j < 4; j++) o[i][j] *= corr;
            Ps[tq * 4 + i][ts]      = pA;
            Ps[tq * 4 + i][ts + 16] = pB;
        }
        __syncthreads();

        // O += P V : 4q x 4d per thread
#pragma unroll 4
        for (int kk = 0; kk < 32; kk += 4) {
            float4 v0 = *reinterpret_cast<const float4*>(&Vs[kk + 0][ts * 4]);
            float4 v1 = *reinterpret_cast<const float4*>(&Vs[kk + 1][ts * 4]);
            float4 v2 = *reinterpret_cast<const float4*>(&Vs[kk + 2][ts * 4]);
            float4 v3 = *reinterpret_cast<const float4*>(&Vs[kk + 3][ts * 4]);
#pragma unroll
            for (int i = 0; i < 4; i++) {
                float4 pp = *reinterpret_cast<const float4*>(&Ps[tq * 4 + i][kk]);
                o[i][0] += pp.x * v0.x + pp.y * v1.x + pp.z * v2.x + pp.w * v3.x;
                o[i][1] += pp.x * v0.y + pp.y * v1.y + pp.z * v2.y + pp.w * v3.y;
                o[i][2] += pp.x * v0.z + pp.y * v1.z + pp.z * v2.z + pp.w * v3.z;
                o[i][3] += pp.x * v0.w + pp.y * v1.w + pp.z * v2.w + pp.w * v3.w;
            }
        }
    }

    // Normalize + write (transposed-concat layout)
#pragma unroll
    for (int i = 0; i < 4; i++) {
        float inv = 1.f / l_i[i];
        int q = qt * 64 + tq * 4 + i;
        size_t off = ((size_t)b * outRows + outRow0 + q) * C_ + h * D_ + ts * 4;
        *reinterpret_cast<float4*>(Out + off) =
            make_float4(o[i][0] * inv, o[i][1] * inv, o[i][2] * inv, o[i][3] * inv);
    }
}

// ---------------------------------------------------------------------------
// Launch
// ---------------------------------------------------------------------------
extern "C" void kernel_launch(void* const* d_in, const int* in_sizes, int n_in,
                              void* d_out, int out_size)
{
    const float* x    = (const float*)d_in[0];
    const float* xh   = (const float*)d_in[1];
    const float* qkvw = (const float*)d_in[2];
    const float* pw   = (const float*)d_in[3];
    const float* pb   = (const float*)d_in[4];

    float* out  = (float*)d_out;
    float* outh = out + (size_t)B_ * NTOK * C_;

    float *Q, *K, *V, *Qh, *Kh, *Vh, *XA, *XSh;
    cudaGetSymbolAddress((void**)&Q,   g_Q);
    cudaGetSymbolAddress((void**)&K,   g_K);
    cudaGetSymbolAddress((void**)&V,   g_V);
    cudaGetSymbolAddress((void**)&Qh,  g_Qh);
    cudaGetSymbolAddress((void**)&Kh,  g_Kh);
    cudaGetSymbolAddress((void**)&Vh,  g_Vh);
    cudaGetSymbolAddress((void**)&XA,  g_XA);
    cudaGetSymbolAddress((void**)&XSh, g_XSh);

    const dim3 blk(256);

    // QKV GEMMs (M=24576, Nc=2304): scatter into [B,H,N,D]
    const dim3 gq(2304 / 128, 24576 / 128);
    gemm_tf32_kernel<0><<<gq, blk>>>(x,  qkvw, Q,  K,  V,  nullptr);
    gemm_tf32_kernel<0><<<gq, blk>>>(xh, qkvw, Qh, Kh, Vh, nullptr);

    // Attention: mt (shared), s, s_hsi
    attn_kernel<<<dim3(2, H_, B_), blk>>>(Q,  K,  V,  XA,  0,   LT,  NTOK, 0);
    attn_kernel<<<dim3(4, H_, B_), blk>>>(Q,  K,  V,  XA,  LT,  NTOK, NTOK, LT);
    attn_kernel<<<dim3(4, H_, B_), blk>>>(Qh, Kh, Vh, XSh, LT,  NTOK, LS,  0);

    // Projection GEMMs (+bias). x_mt rows are projected once, duplicated.
    const dim3 gp1(768 / 128, 24576 / 128);
    gemm_tf32_kernel<1><<<gp1, blk>>>(XA, pw, out, outh, nullptr, pb);
    const dim3 gp2(768 / 128, 16384 / 128);
    gemm_tf32_kernel<2><<<gp2, blk>>>(XSh, pw, outh, nullptr, nullptr, pb);
}

// round 2
// speedup vs baseline: 1.4524x; 1.4524x over previous
#include <cuda_runtime.h>
#include <cstdint>

// ---------------------------------------------------------------------------
// Problem constants
// ---------------------------------------------------------------------------
#define B_   64
#define NTOK 384
#define C_   768
#define H_   12
#define D_   64
#define LT   128
#define LS   256

// ---------------------------------------------------------------------------
// Scratch
// ---------------------------------------------------------------------------
__device__ __align__(16) float g_Q [(size_t)B_ * H_ * NTOK * D_];
__device__ __align__(16) float g_K [(size_t)B_ * H_ * NTOK * D_];
__device__ __align__(16) float g_V [(size_t)B_ * H_ * NTOK * D_];
__device__ __align__(16) float g_Qh[(size_t)B_ * H_ * NTOK * D_];
__device__ __align__(16) float g_Kh[(size_t)B_ * H_ * NTOK * D_];
__device__ __align__(16) float g_Vh[(size_t)B_ * H_ * NTOK * D_];
__device__ __align__(16) float g_XA [(size_t)B_ * NTOK * C_];
__device__ __align__(16) float g_XSh[(size_t)B_ * LS   * C_];

// ---------------------------------------------------------------------------
// tf32 helpers
// ---------------------------------------------------------------------------
__device__ __forceinline__ unsigned f2tf32(float x) {
    unsigned r;
    asm("cvt.rna.tf32.f32 %0, %1;" : "=r"(r) : "f"(x));
    return r;
}

__device__ __forceinline__ float ex2f(float x) {
    float y;
    asm("ex2.approx.ftz.f32 %0, %1;" : "=f"(y) : "f"(x));
    return y;
}

__device__ __forceinline__ void mma_tf32(float c[4],
    unsigned a0, unsigned a1, unsigned a2, unsigned a3,
    unsigned b0, unsigned b1)
{
    asm volatile(
        "mma.sync.aligned.m16n8k8.row.col.f32.tf32.tf32.f32 "
        "{%0,%1,%2,%3}, {%4,%5,%6,%7}, {%8,%9}, {%0,%1,%2,%3};\n"
        : "+f"(c[0]), "+f"(c[1]), "+f"(c[2]), "+f"(c[3])
        : "r"(a0), "r"(a1), "r"(a2), "r"(a3), "r"(b0), "r"(b1));
}

// ---------------------------------------------------------------------------
// GEMM: C[M,Nc] = A[M,768] * W[Nc,768]^T  (tf32 MMA, fp32 accum)
// Double-buffered smem (kb=16), register prefetch, one sync per iter.
// MODE 0: QKV scatter  MODE 1: proj->out (+dup mt rows to outh)  MODE 2: proj->outh
// ---------------------------------------------------------------------------
template <int MODE>
__global__ __launch_bounds__(256, 2)
void gemm_tf32_kernel(const float* __restrict__ A, const float* __restrict__ W,
                      float* __restrict__ p0, float* __restrict__ p1,
                      float* __restrict__ p2, const float* __restrict__ bias)
{
    __shared__ unsigned As[2][128][20];
    __shared__ unsigned Bs[2][128][20];

    const int bm  = blockIdx.y * 128;
    const int bn  = blockIdx.x * 128;
    const int tid = threadIdx.x;
    const int wid = tid >> 5, lane = tid & 31;
    const int wm  = wid & 3, wn = wid >> 2;          // warp tile 32m x 64n
    const int gid = lane >> 2, tig = lane & 3;

    const int lr = tid >> 2;               // 0..63
    const int lc = (tid & 3) << 2;         // 0,4,8,12

    const float* Ap0 = A + (size_t)(bm + lr)      * 768 + lc;
    const float* Ap1 = A + (size_t)(bm + lr + 64) * 768 + lc;
    const float* Bp0 = W + (size_t)(bn + lr)      * 768 + lc;
    const float* Bp1 = W + (size_t)(bn + lr + 64) * 768 + lc;

    float acc[2][8][4];
#pragma unroll
    for (int a = 0; a < 2; a++)
#pragma unroll
        for (int b = 0; b < 8; b++)
#pragma unroll
            for (int c = 0; c < 4; c++) acc[a][b][c] = 0.f;

    float4 pa0, pa1, pb0, pb1;

    // prologue: load tile 0
    pa0 = *reinterpret_cast<const float4*>(Ap0);
    pa1 = *reinterpret_cast<const float4*>(Ap1);
    pb0 = *reinterpret_cast<const float4*>(Bp0);
    pb1 = *reinterpret_cast<const float4*>(Bp1);
    *reinterpret_cast<uint4*>(&As[0][lr     ][lc]) = make_uint4(f2tf32(pa0.x), f2tf32(pa0.y), f2tf32(pa0.z), f2tf32(pa0.w));
    *reinterpret_cast<uint4*>(&As[0][lr + 64][lc]) = make_uint4(f2tf32(pa1.x), f2tf32(pa1.y), f2tf32(pa1.z), f2tf32(pa1.w));
    *reinterpret_cast<uint4*>(&Bs[0][lr     ][lc]) = make_uint4(f2tf32(pb0.x), f2tf32(pb0.y), f2tf32(pb0.z), f2tf32(pb0.w));
    *reinterpret_cast<uint4*>(&Bs[0][lr + 64][lc]) = make_uint4(f2tf32(pb1.x), f2tf32(pb1.y), f2tf32(pb1.z), f2tf32(pb1.w));
    __syncthreads();

    int buf = 0;
    for (int kb = 0; kb < 768; kb += 16) {
        const bool more = (kb + 16) < 768;
        if (more) {
            pa0 = *reinterpret_cast<const float4*>(Ap0 + kb + 16);
            pa1 = *reinterpret_cast<const float4*>(Ap1 + kb + 16);
            pb0 = *reinterpret_cast<const float4*>(Bp0 + kb + 16);
            pb1 = *reinterpret_cast<const float4*>(Bp1 + kb + 16);
        }
#pragma unroll
        for (int ks = 0; ks < 2; ks++) {
            const int k0 = ks * 8;
            unsigned af[2][4], bf[8][2];
#pragma unroll
            for (int mi = 0; mi < 2; mi++) {
                int m = wm * 32 + mi * 16;
                af[mi][0] = As[buf][m + gid    ][k0 + tig];
                af[mi][1] = As[buf][m + gid + 8][k0 + tig];
                af[mi][2] = As[buf][m + gid    ][k0 + tig + 4];
                af[mi][3] = As[buf][m + gid + 8][k0 + tig + 4];
            }
#pragma unroll
            for (int ni = 0; ni < 8; ni++) {
                int n = wn * 64 + ni * 8;
                bf[ni][0] = Bs[buf][n + gid][k0 + tig];
                bf[ni][1] = Bs[buf][n + gid][k0 + tig + 4];
            }
#pragma unroll
            for (int mi = 0; mi < 2; mi++)
#pragma unroll
                for (int ni = 0; ni < 8; ni++)
                    mma_tf32(acc[mi][ni], af[mi][0], af[mi][1], af[mi][2], af[mi][3],
                             bf[ni][0], bf[ni][1]);
        }
        if (more) {
            const int nb = buf ^ 1;
            *reinterpret_cast<uint4*>(&As[nb][lr     ][lc]) = make_uint4(f2tf32(pa0.x), f2tf32(pa0.y), f2tf32(pa0.z), f2tf32(pa0.w));
            *reinterpret_cast<uint4*>(&As[nb][lr + 64][lc]) = make_uint4(f2tf32(pa1.x), f2tf32(pa1.y), f2tf32(pa1.z), f2tf32(pa1.w));
            *reinterpret_cast<uint4*>(&Bs[nb][lr     ][lc]) = make_uint4(f2tf32(pb0.x), f2tf32(pb0.y), f2tf32(pb0.z), f2tf32(pb0.w));
            *reinterpret_cast<uint4*>(&Bs[nb][lr + 64][lc]) = make_uint4(f2tf32(pb1.x), f2tf32(pb1.y), f2tf32(pb1.z), f2tf32(pb1.w));
        }
        __syncthreads();
        buf ^= 1;
    }

    // epilogue
#pragma unroll
    for (int mi = 0; mi < 2; mi++) {
#pragma unroll
        for (int ni = 0; ni < 8; ni++) {
            const int row = bm + wm * 32 + mi * 16 + gid;
            const int col = bn + wn * 64 + ni * 8 + tig * 2;
#pragma unroll
            for (int half = 0; half < 2; half++) {
                const int r  = row + half * 8;
                const float v0 = acc[mi][ni][half * 2 + 0];
                const float v1 = acc[mi][ni][half * 2 + 1];
                if (MODE == 0) {
                    int t = col / 768;
                    int rem = col - t * 768;
                    int h = rem >> 6, d = rem & 63;
                    int b = r / 384, n = r - b * 384;
                    float* dst = (t == 0) ? p0 : ((t == 1) ? p1 : p2);
                    *reinterpret_cast<float2*>(
                        dst + ((((size_t)b * H_ + h) * NTOK + n) << 6) + d) =
                        make_float2(v0, v1);
                } else if (MODE == 1) {
                    float2 v = make_float2(v0 + bias[col], v1 + bias[col + 1]);
                    *reinterpret_cast<float2*>(p0 + (size_t)r * 768 + col) = v;
                    int n = r - (r / 384) * 384;
                    if (n < LT)
                        *reinterpret_cast<float2*>(p1 + (size_t)r * 768 + col) = v;
                } else {
                    float2 v = make_float2(v0 + bias[col], v1 + bias[col + 1]);
                    int b = r >> 8;
                    int q = r & 255;
                    *reinterpret_cast<float2*>(
                        p0 + ((size_t)b * NTOK + LT + q) * 768 + col) = v;
                }
            }
        }
    }
}

// ---------------------------------------------------------------------------
// Tensor-core flash attention (tf32 mma, fp32 softmax/accum).
// CTA = 128 queries of one (b,h). 8 warps, warp owns 16 q rows.
// K/V streamed in 64-key chunks. P relaid out A-fragment-wise via shuffles.
// ---------------------------------------------------------------------------
__global__ __launch_bounds__(256, 2)
void attn_tc_kernel(const float* __restrict__ Qt, const float* __restrict__ Kt,
                    const float* __restrict__ Vt, float* __restrict__ Out,
                    int q0, int Lk, int outRows, int outRow0)
{
    __shared__ unsigned sm[64 * 68 + 64 * 72];
    unsigned (*Ks)[68] = (unsigned(*)[68])sm;
    unsigned (*Vs)[72] = (unsigned(*)[72])(sm + 64 * 68);
    float    (*Qs)[68] = (float(*)[68])sm;           // staging (128x68 fits)

    const int tid = threadIdx.x, wid = tid >> 5, lane = tid & 31;
    const int gid = lane >> 2, tig = lane & 3;
    const int h = blockIdx.y, b = blockIdx.z;
    const int wq = wid * 16;

    const float qscale = 0.125f * 1.4426950408889634f;  // Dh^-0.5 * log2(e)

    const float* Qbh = Qt + (((size_t)b * H_ + h) * NTOK + q0 + blockIdx.x * 128) * D_;
    const float* Kbh = Kt + (((size_t)b * H_ + h) * NTOK) * D_;
    const float* Vbh = Vt + (((size_t)b * H_ + h) * NTOK) * D_;

    // stage Q (scaled), build per-warp A-fragments
#pragma unroll
    for (int i = 0; i < 8; i++) {
        int idx = tid + i * 256;
        int r = idx >> 4, c4 = (idx & 15) << 2;
        float4 v = *reinterpret_cast<const float4*>(Qbh + r * D_ + c4);
        v.x *= qscale; v.y *= qscale; v.z *= qscale; v.w *= qscale;
        *reinterpret_cast<float4*>(&Qs[r][c4]) = v;
    }
    __syncthreads();

    unsigned qf[8][4];
#pragma unroll
    for (int ks = 0; ks < 8; ks++) {
        qf[ks][0] = f2tf32(Qs[wq + gid    ][8 * ks + tig]);
        qf[ks][1] = f2tf32(Qs[wq + gid + 8][8 * ks + tig]);
        qf[ks][2] = f2tf32(Qs[wq + gid    ][8 * ks + tig + 4]);
        qf[ks][3] = f2tf32(Qs[wq + gid + 8][8 * ks + tig + 4]);
    }

    float o[8][4];
#pragma unroll
    for (int nt = 0; nt < 8; nt++)
#pragma unroll
        for (int c = 0; c < 4; c++) o[nt][c] = 0.f;
    float m0 = -1e30f, m1 = -1e30f, l0 = 0.f, l1 = 0.f;

    const int  srcA = (lane & ~3) | (tig >> 1);
    const int  srcB = srcA + 2;
    const bool hi   = (tig & 1);

    for (int kb = 0; kb < Lk; kb += 64) {
        __syncthreads();   // all warps done with previous K/V (and Q staging)
#pragma unroll
        for (int i = 0; i < 4; i++) {
            int idx = tid + i * 256;
            int r = idx >> 4, c4 = (idx & 15) << 2;
            float4 kv = *reinterpret_cast<const float4*>(Kbh + (size_t)(kb + r) * D_ + c4);
            *reinterpret_cast<uint4*>(&Ks[r][c4]) =
                make_uint4(f2tf32(kv.x), f2tf32(kv.y), f2tf32(kv.z), f2tf32(kv.w));
            float4 vv = *reinterpret_cast<const float4*>(Vbh + (size_t)(kb + r) * D_ + c4);
            *reinterpret_cast<uint4*>(&Vs[r][c4]) =
                make_uint4(f2tf32(vv.x), f2tf32(vv.y), f2tf32(vv.z), f2tf32(vv.w));
        }
        __syncthreads();

        // S = Q K^T   (16 rows x 64 keys per warp)
        float s[8][4];
#pragma unroll
        for (int nt = 0; nt < 8; nt++)
#pragma unroll
            for (int c = 0; c < 4; c++) s[nt][c] = 0.f;
#pragma unroll
        for (int ks = 0; ks < 8; ks++) {
#pragma unroll
            for (int nt = 0; nt < 8; nt++) {
                unsigned b0 = Ks[8 * nt + gid][8 * ks + tig];
                unsigned b1 = Ks[8 * nt + gid][8 * ks + tig + 4];
                mma_tf32(s[nt], qf[ks][0], qf[ks][1], qf[ks][2], qf[ks][3], b0, b1);
            }
        }

        // online softmax (rows wq+gid and wq+gid+8); S already in log2 domain
        float mx0 = -1e30f, mx1 = -1e30f;
#pragma unroll
        for (int nt = 0; nt < 8; nt++) {
            mx0 = fmaxf(mx0, fmaxf(s[nt][0], s[nt][1]));
            mx1 = fmaxf(mx1, fmaxf(s[nt][2], s[nt][3]));
        }
        mx0 = fmaxf(mx0, __shfl_xor_sync(0xffffffffu, mx0, 1));
        mx0 = fmaxf(mx0, __shfl_xor_sync(0xffffffffu, mx0, 2));
        mx1 = fmaxf(mx1, __shfl_xor_sync(0xffffffffu, mx1, 1));
        mx1 = fmaxf(mx1, __shfl_xor_sync(0xffffffffu, mx1, 2));

        float mn0 = fmaxf(m0, mx0), mn1 = fmaxf(m1, mx1);
        float cr0 = ex2f(m0 - mn0), cr1 = ex2f(m1 - mn1);
        float ls0 = 0.f, ls1 = 0.f;
#pragma unroll
        for (int nt = 0; nt < 8; nt++) {
            s[nt][0] = ex2f(s[nt][0] - mn0);
            s[nt][1] = ex2f(s[nt][1] - mn0);
            s[nt][2] = ex2f(s[nt][2] - mn1);
            s[nt][3] = ex2f(s[nt][3] - mn1);
            ls0 += s[nt][0] + s[nt][1];
            ls1 += s[nt][2] + s[nt][3];
        }
        ls0 += __shfl_xor_sync(0xffffffffu, ls0, 1);
        ls0 += __shfl_xor_sync(0xffffffffu, ls0, 2);
        ls1 += __shfl_xor_sync(0xffffffffu, ls1, 1);
        ls1 += __shfl_xor_sync(0xffffffffu, ls1, 2);
        l0 = l0 * cr0 + ls0;  m0 = mn0;
        l1 = l1 * cr1 + ls1;  m1 = mn1;
#pragma unroll
        for (int nt = 0; nt < 8; nt++) {
            o[nt][0] *= cr0; o[nt][1] *= cr0;
            o[nt][2] *= cr1; o[nt][3] *= cr1;
        }

        // O += P V : per k-step j, build P A-fragment via in-warp shuffles
#pragma unroll
        for (int j = 0; j < 8; j++) {
            unsigned pj0 = f2tf32(s[j][0]), pj1 = f2tf32(s[j][1]);
            unsigned pj2 = f2tf32(s[j][2]), pj3 = f2tf32(s[j][3]);
            unsigned x0 = __shfl_sync(0xffffffffu, pj0, srcA);
            unsigned x1 = __shfl_sync(0xffffffffu, pj1, srcA);
            unsigned x2 = __shfl_sync(0xffffffffu, pj2, srcA);
            unsigned x3 = __shfl_sync(0xffffffffu, pj3, srcA);
            unsigned y0 = __shfl_sync(0xffffffffu, pj0, srcB);
            unsigned y1 = __shfl_sync(0xffffffffu, pj1, srcB);
            unsigned y2 = __shfl_sync(0xffffffffu, pj2, srcB);
            unsigned y3 = __shfl_sync(0xffffffffu, pj3, srcB);
            unsigned a0 = hi ? x1 : x0;
            unsigned a1 = hi ? x3 : x2;
            unsigned a2 = hi ? y1 : y0;
            unsigned a3 = hi ? y3 : y2;
#pragma unroll
            for (int nt = 0; nt < 8; nt++) {
                unsigned b0 = Vs[8 * j + tig    ][8 * nt + gid];
                unsigned b1 = Vs[8 * j + tig + 4][8 * nt + gid];
                mma_tf32(o[nt], a0, a1, a2, a3, b0, b1);
            }
        }
    }

    // normalize + write (transposed-concat layout)
    float inv0 = 1.f / l0, inv1 = 1.f / l1;
    int r0g = outRow0 + blockIdx.x * 128 + wq + gid;
    float* Ob = Out + ((size_t)b * outRows + r0g) * C_ + h * D_;
#pragma unroll
    for (int nt = 0; nt < 8; nt++) {
        *reinterpret_cast<float2*>(Ob + 8 * nt + 2 * tig) =
            make_float2(o[nt][0] * inv0, o[nt][1] * inv0);
        *reinterpret_cast<float2*>(Ob + (size_t)8 * C_ + 8 * nt + 2 * tig) =
            make_float2(o[nt][2] * inv1, o[nt][3] * inv1);
    }
}

// ---------------------------------------------------------------------------
// Launch
// ---------------------------------------------------------------------------
extern "C" void kernel_launch(void* const* d_in, const int* in_sizes, int n_in,
                              void* d_out, int out_size)
{
    const float* x    = (const float*)d_in[0];
    const float* xh   = (const float*)d_in[1];
    const float* qkvw = (const float*)d_in[2];
    const float* pw   = (const float*)d_in[3];
    const float* pb   = (const float*)d_in[4];

    float* out  = (float*)d_out;
    float* outh = out + (size_t)B_ * NTOK * C_;

    float *Q, *K, *V, *Qh, *Kh, *Vh, *XA, *XSh;
    cudaGetSymbolAddress((void**)&Q,   g_Q);
    cudaGetSymbolAddress((void**)&K,   g_K);
    cudaGetSymbolAddress((void**)&V,   g_V);
    cudaGetSymbolAddress((void**)&Qh,  g_Qh);
    cudaGetSymbolAddress((void**)&Kh,  g_Kh);
    cudaGetSymbolAddress((void**)&Vh,  g_Vh);
    cudaGetSymbolAddress((void**)&XA,  g_XA);
    cudaGetSymbolAddress((void**)&XSh, g_XSh);

    const dim3 blk(256);

    // QKV GEMMs
    const dim3 gq(2304 / 128, 24576 / 128);
    gemm_tf32_kernel<0><<<gq, blk>>>(x,  qkvw, Q,  K,  V,  nullptr);
    gemm_tf32_kernel<0><<<gq, blk>>>(xh, qkvw, Qh, Kh, Vh, nullptr);

    // Attention
    attn_tc_kernel<<<dim3(1, H_, B_), blk>>>(Q,  K,  V,  XA,  0,  LT,   NTOK, 0);
    attn_tc_kernel<<<dim3(2, H_, B_), blk>>>(Q,  K,  V,  XA,  LT, NTOK, NTOK, LT);
    attn_tc_kernel<<<dim3(2, H_, B_), blk>>>(Qh, Kh, Vh, XSh, LT, NTOK, LS,   0);

    // Projection GEMMs
    const dim3 gp1(768 / 128, 24576 / 128);
    gemm_tf32_kernel<1><<<gp1, blk>>>(XA, pw, out, outh, nullptr, pb);
    const dim3 gp2(768 / 128, 16384 / 128);
    gemm_tf32_kernel<2><<<gp2, blk>>>(XSh, pw, outh, nullptr, nullptr, pb);
}

// round 4
// speedup vs baseline: 3.2729x; 2.2534x over previous
#include <cuda_runtime.h>
#include <cuda_fp16.h>
#include <cstdint>

// ---------------------------------------------------------------------------
// Problem constants
// ---------------------------------------------------------------------------
#define B_   64
#define NTOK 384
#define C_   768
#define H_   12
#define D_   64
#define LT   128
#define LS   256

// ---------------------------------------------------------------------------
// Scratch (all half)
// ---------------------------------------------------------------------------
__device__ __align__(16) __half g_Q  [(size_t)B_ * H_ * NTOK * D_];
__device__ __align__(16) __half g_K  [(size_t)B_ * H_ * NTOK * D_];
__device__ __align__(16) __half g_V  [(size_t)B_ * H_ * NTOK * D_];
__device__ __align__(16) __half g_Qh [(size_t)B_ * H_ * NTOK * D_];
__device__ __align__(16) __half g_Kh [(size_t)B_ * H_ * NTOK * D_];
__device__ __align__(16) __half g_Vh [(size_t)B_ * H_ * NTOK * D_];
__device__ __align__(16) __half g_XA [(size_t)B_ * NTOK * C_];
__device__ __align__(16) __half g_XSh[(size_t)B_ * LS   * C_];
__device__ __align__(16) __half g_Xr [(size_t)B_ * NTOK * C_];
__device__ __align__(16) __half g_Xhr[(size_t)B_ * NTOK * C_];
__device__ __align__(16) __half g_Wq [(size_t)3 * C_ * C_];
__device__ __align__(16) __half g_Wp [(size_t)C_ * C_];

// ---------------------------------------------------------------------------
// helpers
// ---------------------------------------------------------------------------
__device__ __forceinline__ float ex2f(float x) {
    float y;
    asm("ex2.approx.ftz.f32 %0, %1;" : "=f"(y) : "f"(x));
    return y;
}
__device__ __forceinline__ uint32_t h2u(__half2 h) {
    return *reinterpret_cast<uint32_t*>(&h);
}
__device__ __forceinline__ void mma_f16(float c[4],
    uint32_t a0, uint32_t a1, uint32_t a2, uint32_t a3,
    uint32_t b0, uint32_t b1)
{
    asm volatile(
        "mma.sync.aligned.m16n8k16.row.col.f32.f16.f16.f32 "
        "{%0,%1,%2,%3}, {%4,%5,%6,%7}, {%8,%9}, {%0,%1,%2,%3};\n"
        : "+f"(c[0]), "+f"(c[1]), "+f"(c[2]), "+f"(c[3])
        : "r"(a0), "r"(a1), "r"(a2), "r"(a3), "r"(b0), "r"(b1));
}
__device__ __forceinline__ uint32_t smem_u32(const void* p) {
    uint32_t a;
    asm("{ .reg .u64 t; cvta.to.shared.u64 t, %1; cvt.u32.u64 %0, t; }" : "=r"(a) : "l"(p));
    return a;
}
__device__ __forceinline__ void ldsm4(uint32_t& r0, uint32_t& r1, uint32_t& r2, uint32_t& r3,
                                      uint32_t addr) {
    asm volatile("ldmatrix.sync.aligned.m8n8.x4.shared.b16 {%0,%1,%2,%3}, [%4];"
                 : "=r"(r0), "=r"(r1), "=r"(r2), "=r"(r3) : "r"(addr));
}
__device__ __forceinline__ void ldsm4t(uint32_t& r0, uint32_t& r1, uint32_t& r2, uint32_t& r3,
                                       uint32_t addr) {
    asm volatile("ldmatrix.sync.aligned.m8n8.x4.trans.shared.b16 {%0,%1,%2,%3}, [%4];"
                 : "=r"(r0), "=r"(r1), "=r"(r2), "=r"(r3) : "r"(addr));
}
__device__ __forceinline__ void cp16(uint32_t dst, const void* src) {
    asm volatile("cp.async.cg.shared.global [%0], [%1], 16;\n" :: "r"(dst), "l"(src) : "memory");
}
__device__ __forceinline__ void cp_commit() { asm volatile("cp.async.commit_group;\n" ::: "memory"); }

#define QS_CONST (0.125f * 1.4426950408889634f)   // Dh^-0.5 * log2(e)

// ---------------------------------------------------------------------------
// fp16 GEMM: C[M,Nc] = A[M,768] * W[Nc,768]^T   (fp32 accum)
// CTA 128x128, kb=32, 3-stage cp.async, ldmatrix fragments.
// MODE 0: QKV scatter (Q pre-scaled by QS_CONST), half outputs
// MODE 1: proj -> out fp32 (+bias), dup rows n<LT to outh
// MODE 2: proj -> outh rows LT.. fp32 (+bias)
// ---------------------------------------------------------------------------
#define GSTRIDE 40                       // halves per smem row
#define A_ST    (128 * GSTRIDE * 2)      // 10240 B
#define STG     (2 * A_ST)               // 20480 B per stage
#define GEMM_SMEM (3 * STG)              // 61440 B

template <int MODE>
__global__ __launch_bounds__(256, 2)
void gemm_h_kernel(const __half* __restrict__ A, const __half* __restrict__ W,
                   void* __restrict__ p0v, void* __restrict__ p1v,
                   void* __restrict__ p2v, const float* __restrict__ bias)
{
    extern __shared__ __half hsm[];
    const uint32_t sbase = smem_u32(hsm);

    const int tid  = threadIdx.x;
    const int wid  = tid >> 5, lane = tid & 31;
    const int wm   = wid & 3, wn = wid >> 2;      // warp tile 32m x 64n
    const int bm   = blockIdx.y * 128;
    const int bn   = blockIdx.x * 128;

    // cp.async: per thread 2 A-chunks + 2 B-chunks of 16B per stage
    uint32_t offA[2], offB[2];
    const char* srcA[2];
    const char* srcB[2];
#pragma unroll
    for (int j = 0; j < 2; j++) {
        int id = tid + j * 256;
        int r = id >> 2, c = id & 3;
        offA[j] = (uint32_t)((r * GSTRIDE + c * 8) * 2);
        offB[j] = offA[j] + A_ST;
        srcA[j] = (const char*)(A + (size_t)(bm + r) * 768 + c * 8);
        srcB[j] = (const char*)(W + (size_t)(bn + r) * 768 + c * 8);
    }

#define G_LOAD(st, kh)                                                        \
    do {                                                                      \
        uint32_t base = sbase + (st) * STG;                                   \
        _Pragma("unroll")                                                     \
        for (int j = 0; j < 2; j++) {                                         \
            cp16(base + offA[j], srcA[j] + (size_t)(kh) * 2);                 \
            cp16(base + offB[j], srcB[j] + (size_t)(kh) * 2);                 \
        }                                                                     \
        cp_commit();                                                          \
    } while (0)

    // ldmatrix offsets (bytes within stage)
    uint32_t aoff[2][2], boff[4][2];
#pragma unroll
    for (int mi = 0; mi < 2; mi++)
#pragma unroll
        for (int ks = 0; ks < 2; ks++) {
            int row = wm * 32 + mi * 16 + (lane & 15);
            int col = ks * 16 + ((lane >> 4) << 3);
            aoff[mi][ks] = (uint32_t)((row * GSTRIDE + col) * 2);
        }
#pragma unroll
    for (int p = 0; p < 4; p++)
#pragma unroll
        for (int ks = 0; ks < 2; ks++) {
            int row = wn * 64 + p * 16 + (lane & 7) + ((lane >> 4) & 1) * 8;
            int col = ks * 16 + ((lane >> 3) & 1) * 8;
            boff[p][ks] = (uint32_t)(A_ST + (row * GSTRIDE + col) * 2);
        }

    float acc[2][8][4];
#pragma unroll
    for (int a = 0; a < 2; a++)
#pragma unroll
        for (int b = 0; b < 8; b++)
#pragma unroll
            for (int c = 0; c < 4; c++) acc[a][b][c] = 0.f;

    G_LOAD(0, 0);
    G_LOAD(1, 32);

#pragma unroll 1
    for (int i = 0; i < 24; i++) {
        if (i < 23) asm volatile("cp.async.wait_group 1;\n" ::: "memory");
        else        asm volatile("cp.async.wait_group 0;\n" ::: "memory");
        __syncthreads();

        const uint32_t base = sbase + (i % 3) * STG;
#pragma unroll
        for (int ks = 0; ks < 2; ks++) {
            uint32_t a[2][4], bf[8][2];
#pragma unroll
            for (int mi = 0; mi < 2; mi++)
                ldsm4(a[mi][0], a[mi][1], a[mi][2], a[mi][3], base + aoff[mi][ks]);
#pragma unroll
            for (int p = 0; p < 4; p++) {
                uint32_t r0, r1, r2, r3;
                ldsm4(r0, r1, r2, r3, base + boff[p][ks]);
                bf[2 * p][0] = r0; bf[2 * p][1] = r1;
                bf[2 * p + 1][0] = r2; bf[2 * p + 1][1] = r3;
            }
#pragma unroll
            for (int mi = 0; mi < 2; mi++)
#pragma unroll
                for (int ni = 0; ni < 8; ni++)
                    mma_f16(acc[mi][ni], a[mi][0], a[mi][1], a[mi][2], a[mi][3],
                            bf[ni][0], bf[ni][1]);
        }
        if (i + 2 < 24) G_LOAD((i + 2) % 3, (i + 2) * 32);
    }

    // ---- epilogue
#pragma unroll
    for (int mi = 0; mi < 2; mi++) {
#pragma unroll
        for (int ni = 0; ni < 8; ni++) {
            const int row = bm + wm * 32 + mi * 16 + (lane >> 2);
            const int col = bn + wn * 64 + ni * 8 + ((lane & 3) << 1);
#pragma unroll
            for (int hf = 0; hf < 2; hf++) {
                const int r = row + hf * 8;
                float v0 = acc[mi][ni][hf * 2 + 0];
                float v1 = acc[mi][ni][hf * 2 + 1];
                if (MODE == 0) {
                    int t = col / 768;
                    int rem = col - t * 768;
                    int h = rem >> 6, d = rem & 63;
                    int b = r / 384, n = r - b * 384;
                    if (t == 0) { v0 *= QS_CONST; v1 *= QS_CONST; }
                    __half* dst = (t == 0) ? (__half*)p0v : ((t == 1) ? (__half*)p1v : (__half*)p2v);
                    *reinterpret_cast<__half2*>(
                        dst + ((((size_t)b * H_ + h) * NTOK + n) << 6) + d) =
                        __floats2half2_rn(v0, v1);
                } else if (MODE == 1) {
                    float2 v = make_float2(v0 + bias[col], v1 + bias[col + 1]);
                    *reinterpret_cast<float2*>((float*)p0v + (size_t)r * 768 + col) = v;
                    int n = r - (r / 384) * 384;
                    if (n < LT)
                        *reinterpret_cast<float2*>((float*)p1v + (size_t)r * 768 + col) = v;
                } else {
                    float2 v = make_float2(v0 + bias[col], v1 + bias[col + 1]);
                    int b = r >> 8, q = r & 255;
                    *reinterpret_cast<float2*>(
                        (float*)p0v + ((size_t)b * NTOK + LT + q) * 768 + col) = v;
                }
            }
        }
    }
}

// ---------------------------------------------------------------------------
// fp32 -> fp16 convert
// ---------------------------------------------------------------------------
__global__ void f2h_kernel(const float* __restrict__ in, __half* __restrict__ out, int n4)
{
    int i = blockIdx.x * blockDim.x + threadIdx.x;
    if (i < n4) {
        float4 v = reinterpret_cast<const float4*>(in)[i];
        __half2 a = __floats2half2_rn(v.x, v.y);
        __half2 b = __floats2half2_rn(v.z, v.w);
        reinterpret_cast<uint2*>(out)[i] = make_uint2(h2u(a), h2u(b));
    }
}

// ---------------------------------------------------------------------------
// fp16 tensor-core flash attention. CTA = 128 q rows of one (b,h); 8 warps x 16q.
// 64-key chunks. Q pre-scaled (incl. log2e) at QKV epilogue. Output: half.
// ---------------------------------------------------------------------------
#define KSTR 72          // halves per K/V smem row

__global__ __launch_bounds__(256, 2)
void attn_h_kernel(const __half* __restrict__ Qt, const __half* __restrict__ Kt,
                   const __half* __restrict__ Vt, __half* __restrict__ Out,
                   int q0, int Lk, int outRows, int outRow0)
{
    __shared__ __align__(16) __half sm[2 * 64 * KSTR];
    __half* Ks  = sm;
    __half* Vs  = sm + 64 * KSTR;
    __half* Qst = sm;                       // staging: 128 rows x KSTR

    const int tid = threadIdx.x, wid = tid >> 5, lane = tid & 31;
    const int h = blockIdx.y, b = blockIdx.z;
    const int wq = wid * 16;
    const uint32_t sb = smem_u32(sm);

    const __half* Qbh = Qt + (((size_t)b * H_ + h) * NTOK + q0 + blockIdx.x * 128) * D_;
    const __half* Kbh = Kt + (((size_t)b * H_ + h) * NTOK) * D_;
    const __half* Vbh = Vt + (((size_t)b * H_ + h) * NTOK) * D_;

    // stage Q
#pragma unroll
    for (int i = 0; i < 4; i++) {
        int id = tid + i * 256;
        int r = id >> 3, c = (id & 7) << 3;
        *reinterpret_cast<uint4*>(&Qst[r * KSTR + c]) =
            *reinterpret_cast<const uint4*>(Qbh + r * D_ + c);
    }
    __syncthreads();

    // Q A-fragments (4 ksteps of 16 over D=64)
    uint32_t qf[4][4];
    {
        const int m = wq + (lane >> 2);
        const int c2 = (lane & 3) << 1;
#pragma unroll
        for (int ks = 0; ks < 4; ks++) {
            qf[ks][0] = *reinterpret_cast<uint32_t*>(&Qst[m * KSTR + ks * 16 + c2]);
            qf[ks][1] = *reinterpret_cast<uint32_t*>(&Qst[(m + 8) * KSTR + ks * 16 + c2]);
            qf[ks][2] = *reinterpret_cast<uint32_t*>(&Qst[m * KSTR + ks * 16 + c2 + 8]);
            qf[ks][3] = *reinterpret_cast<uint32_t*>(&Qst[(m + 8) * KSTR + ks * 16 + c2 + 8]);
        }
    }

    // ldmatrix byte offsets
    uint32_t koff[4][4], voff[4][4];
#pragma unroll
    for (int p = 0; p < 4; p++)
#pragma unroll
        for (int ks = 0; ks < 4; ks++) {
            int row = p * 16 + (lane & 7) + ((lane >> 4) & 1) * 8;
            int col = ks * 16 + ((lane >> 3) & 1) * 8;
            koff[p][ks] = (uint32_t)((row * KSTR + col) * 2);
        }
#pragma unroll
    for (int j = 0; j < 4; j++)
#pragma unroll
        for (int f = 0; f < 4; f++) {
            int row = j * 16 + (lane & 7) + ((lane >> 3) & 1) * 8;
            int col = f * 16 + ((lane >> 4) & 1) * 8;
            voff[j][f] = (uint32_t)(64 * KSTR * 2 + (row * KSTR + col) * 2);
        }

    float o[8][4];
#pragma unroll
    for (int nt = 0; nt < 8; nt++)
#pragma unroll
        for (int c = 0; c < 4; c++) o[nt][c] = 0.f;
    float m0 = -1e30f, m1 = -1e30f, l0 = 0.f, l1 = 0.f;

#pragma unroll 1
    for (int kb = 0; kb < Lk; kb += 64) {
        __syncthreads();
#pragma unroll
        for (int i = 0; i < 2; i++) {
            int id = tid + i * 256;
            int r = id >> 3, c = (id & 7) << 3;
            *reinterpret_cast<uint4*>(&Ks[r * KSTR + c]) =
                *reinterpret_cast<const uint4*>(Kbh + (size_t)(kb + r) * D_ + c);
            *reinterpret_cast<uint4*>(&Vs[r * KSTR + c]) =
                *reinterpret_cast<const uint4*>(Vbh + (size_t)(kb + r) * D_ + c);
        }
        __syncthreads();

        // S = Q K^T
        float s[8][4];
#pragma unroll
        for (int nt = 0; nt < 8; nt++)
#pragma unroll
            for (int c = 0; c < 4; c++) s[nt][c] = 0.f;
#pragma unroll
        for (int ks = 0; ks < 4; ks++) {
            uint32_t bf[8][2];
#pragma unroll
            for (int p = 0; p < 4; p++) {
                uint32_t r0, r1, r2, r3;
                ldsm4(r0, r1, r2, r3, sb + koff[p][ks]);
                bf[2 * p][0] = r0; bf[2 * p][1] = r1;
                bf[2 * p + 1][0] = r2; bf[2 * p + 1][1] = r3;
            }
#pragma unroll
            for (int nt = 0; nt < 8; nt++)
                mma_f16(s[nt], qf[ks][0], qf[ks][1], qf[ks][2], qf[ks][3],
                        bf[nt][0], bf[nt][1]);
        }

        // online softmax (log2 domain; scale folded into Q)
        float mx0 = -1e30f, mx1 = -1e30f;
#pragma unroll
        for (int nt = 0; nt < 8; nt++) {
            mx0 = fmaxf(mx0, fmaxf(s[nt][0], s[nt][1]));
            mx1 = fmaxf(mx1, fmaxf(s[nt][2], s[nt][3]));
        }
        mx0 = fmaxf(mx0, __shfl_xor_sync(0xffffffffu, mx0, 1));
        mx0 = fmaxf(mx0, __shfl_xor_sync(0xffffffffu, mx0, 2));
        mx1 = fmaxf(mx1, __shfl_xor_sync(0xffffffffu, mx1, 1));
        mx1 = fmaxf(mx1, __shfl_xor_sync(0xffffffffu, mx1, 2));

        float mn0 = fmaxf(m0, mx0), mn1 = fmaxf(m1, mx1);
        float cr0 = ex2f(m0 - mn0), cr1 = ex2f(m1 - mn1);
        float ls0 = 0.f, ls1 = 0.f;
#pragma unroll
        for (int nt = 0; nt < 8; nt++) {
            s[nt][0] = ex2f(s[nt][0] - mn0);
            s[nt][1] = ex2f(s[nt][1] - mn0);
            s[nt][2] = ex2f(s[nt][2] - mn1);
            s[nt][3] = ex2f(s[nt][3] - mn1);
            ls0 += s[nt][0] + s[nt][1];
            ls1 += s[nt][2] + s[nt][3];
        }
        ls0 += __shfl_xor_sync(0xffffffffu, ls0, 1);
        ls0 += __shfl_xor_sync(0xffffffffu, ls0, 2);
        ls1 += __shfl_xor_sync(0xffffffffu, ls1, 1);
        ls1 += __shfl_xor_sync(0xffffffffu, ls1, 2);
        l0 = l0 * cr0 + ls0;  m0 = mn0;
        l1 = l1 * cr1 + ls1;  m1 = mn1;
#pragma unroll
        for (int nt = 0; nt < 8; nt++) {
            o[nt][0] *= cr0; o[nt][1] *= cr0;
            o[nt][2] *= cr1; o[nt][3] *= cr1;
        }

        // O += P V   (S-accum layout == A-fragment layout: no shuffles)
#pragma unroll
        for (int j = 0; j < 4; j++) {
            uint32_t a0 = h2u(__floats2half2_rn(s[2 * j][0], s[2 * j][1]));
            uint32_t a1 = h2u(__floats2half2_rn(s[2 * j][2], s[2 * j][3]));
            uint32_t a2 = h2u(__floats2half2_rn(s[2 * j + 1][0], s[2 * j + 1][1]));
            uint32_t a3 = h2u(__floats2half2_rn(s[2 * j + 1][2], s[2 * j + 1][3]));
#pragma unroll
            for (int f = 0; f < 4; f++) {
                uint32_t r0, r1, r2, r3;
                ldsm4t(r0, r1, r2, r3, sb + voff[j][f]);
                mma_f16(o[2 * f],     a0, a1, a2, a3, r0, r1);
                mma_f16(o[2 * f + 1], a0, a1, a2, a3, r2, r3);
            }
        }
    }

    // normalize + write half
    float inv0 = 1.f / l0, inv1 = 1.f / l1;
    int r0g = outRow0 + blockIdx.x * 128 + wq + (lane >> 2);
    __half* Ob = Out + ((size_t)b * outRows + r0g) * C_ + h * D_ + ((lane & 3) << 1);
#pragma unroll
    for (int nt = 0; nt < 8; nt++) {
        *reinterpret_cast<__half2*>(Ob + 8 * nt) =
            __floats2half2_rn(o[nt][0] * inv0, o[nt][1] * inv0);
        *reinterpret_cast<__half2*>(Ob + (size_t)8 * C_ + 8 * nt) =
            __floats2half2_rn(o[nt][2] * inv1, o[nt][3] * inv1);
    }
}

// ---------------------------------------------------------------------------
// Launch
// ---------------------------------------------------------------------------
extern "C" void kernel_launch(void* const* d_in, const int* in_sizes, int n_in,
                              void* d_out, int out_size)
{
    const float* x    = (const float*)d_in[0];
    const float* xh   = (const float*)d_in[1];
    const float* qkvw = (const float*)d_in[2];
    const float* pw   = (const float*)d_in[3];
    const float* pb   = (const float*)d_in[4];

    float* out  = (float*)d_out;
    float* outh = out + (size_t)B_ * NTOK * C_;

    __half *Q, *K, *V, *Qh, *Kh, *Vh, *XA, *XSh, *Xr, *Xhr, *Wq, *Wp;
    cudaGetSymbolAddress((void**)&Q,   g_Q);
    cudaGetSymbolAddress((void**)&K,   g_K);
    cudaGetSymbolAddress((void**)&V,   g_V);
    cudaGetSymbolAddress((void**)&Qh,  g_Qh);
    cudaGetSymbolAddress((void**)&Kh,  g_Kh);
    cudaGetSymbolAddress((void**)&Vh,  g_Vh);
    cudaGetSymbolAddress((void**)&XA,  g_XA);
    cudaGetSymbolAddress((void**)&XSh, g_XSh);
    cudaGetSymbolAddress((void**)&Xr,  g_Xr);
    cudaGetSymbolAddress((void**)&Xhr, g_Xhr);
    cudaGetSymbolAddress((void**)&Wq,  g_Wq);
    cudaGetSymbolAddress((void**)&Wp,  g_Wp);

    cudaFuncSetAttribute(gemm_h_kernel<0>, cudaFuncAttributeMaxDynamicSharedMemorySize, GEMM_SMEM);
    cudaFuncSetAttribute(gemm_h_kernel<1>, cudaFuncAttributeMaxDynamicSharedMemorySize, GEMM_SMEM);
    cudaFuncSetAttribute(gemm_h_kernel<2>, cudaFuncAttributeMaxDynamicSharedMemorySize, GEMM_SMEM);

    // fp32 -> fp16 conversions
    {
        int nx = B_ * NTOK * C_ / 4;
        f2h_kernel<<<(nx + 255) / 256, 256>>>(x,  Xr,  nx);
        f2h_kernel<<<(nx + 255) / 256, 256>>>(xh, Xhr, nx);
        int nw = 3 * C_ * C_ / 4;
        f2h_kernel<<<(nw + 255) / 256, 256>>>(qkvw, Wq, nw);
        int np = C_ * C_ / 4;
        f2h_kernel<<<(np + 255) / 256, 256>>>(pw, Wp, np);
    }

    const dim3 blk(256);

    // QKV GEMMs: M=24576, N=2304 -> grid (18, 192)
    gemm_h_kernel<0><<<dim3(18, 192), blk, GEMM_SMEM>>>(Xr,  Wq, Q,  K,  V,  nullptr);
    gemm_h_kernel<0><<<dim3(18, 192), blk, GEMM_SMEM>>>(Xhr, Wq, Qh, Kh, Vh, nullptr);

    // Attention
    attn_h_kernel<<<dim3(1, H_, B_), blk>>>(Q,  K,  V,  XA,  0,  LT,   NTOK, 0);
    attn_h_kernel<<<dim3(2, H_, B_), blk>>>(Q,  K,  V,  XA,  LT, NTOK, NTOK, LT);
    attn_h_kernel<<<dim3(2, H_, B_), blk>>>(Qh, Kh, Vh, XSh, LT, NTOK, LS,   0);

    // Projection GEMMs: N=768 -> 6 n-tiles
    gemm_h_kernel<1><<<dim3(6, 192), blk, GEMM_SMEM>>>(XA,  Wp, out,  outh, nullptr, pb);
    gemm_h_kernel<2><<<dim3(6, 128), blk, GEMM_SMEM>>>(XSh, Wp, outh, nullptr, nullptr, pb);
}